// round 8
// baseline (speedup 1.0000x reference)
#include <cuda_runtime.h>
#include <math_constants.h>

// GraphPoolMol: masked neighborhood max-pool over graph Laplacian sparsity.
// B=64, MAX_ATOM=128, N_FEAT=128.
// out[b,i,f] = max_{j: L[b,i,j]!=0, j<n, i<n} x[b,j,f]; 0 if i>=n.
// diag(L)=1 => for i<n the neighbor set always contains j=i, so padding a
// peel chain with the self row never changes the max, and mask==0 <=> i>=n.
//
// TWO warps per row, each owning 64 features (float2 per lane).
// Warp-autonomous: no smem, no barriers, direct L1/L2-cached gather.

#define AT 128
#define NF 128
#define THREADS 256

__device__ __forceinline__ float2 fmax2(float2 a, float2 b) {
    return make_float2(fmaxf(a.x, b.x), fmaxf(a.y, b.y));
}

// Mlo = (m1<<32)|m0 : bit p<32 -> col 4p,   p>=32 -> col 4(p-32)+1
__device__ __forceinline__ int col_lo(int p) { return ((p & 31) << 2) | (p >> 5); }
// Mhi = (m3<<32)|m2 : bit p<32 -> col 4p+2, p>=32 -> col 4(p-32)+3
__device__ __forceinline__ int col_hi(int p) { return ((p & 31) << 2) + 2 + (p >> 5); }

__global__ __launch_bounds__(THREADS, 6)
void graph_pool_mol_kernel(const float* __restrict__ xg,
                           const float* __restrict__ Lg,
                           const int* __restrict__ mol_slice,
                           float* __restrict__ outg)
{
    const int gw   = (blockIdx.x * THREADS + threadIdx.x) >> 5; // global warp
    const int lane = threadIdx.x & 31;
    const int r    = gw >> 1;                 // row id, 0..8191
    const int h    = gw & 1;                  // feature half, 0..1
    const int b    = r >> 7;                  // batch
    const int i    = r & (AT - 1);            // row within batch

    const int n = __ldg(mol_slice + 2 * b);   // mol_slice[b,0] = n_atoms

    // This warp's 64-feature slice of the output row.
    float2* outw = reinterpret_cast<float2*>(outg)
                 + ((size_t)b * AT + i) * 64 + h * 32;

    if (i >= n) {                             // padded row: zeros
        outw[lane] = make_float2(0.f, 0.f);
        return;
    }

    // ---- Load L row (coalesced float4/lane), build two 64-bit masks -------
    const float4 Lv = __ldg(reinterpret_cast<const float4*>(
                                Lg + ((size_t)b * AT + i) * AT) + lane);
    const int j0 = 4 * lane;
    const unsigned m0 = __ballot_sync(0xffffffffu, (Lv.x != 0.f) && (j0 + 0 < n));
    const unsigned m1 = __ballot_sync(0xffffffffu, (Lv.y != 0.f) && (j0 + 1 < n));
    const unsigned m2 = __ballot_sync(0xffffffffu, (Lv.z != 0.f) && (j0 + 2 < n));
    const unsigned m3 = __ballot_sync(0xffffffffu, (Lv.w != 0.f) && (j0 + 3 < n));

    unsigned long long Mlo = ((unsigned long long)m1 << 32) | m0;
    unsigned long long Mhi = ((unsigned long long)m3 << 32) | m2;
    const int kmax = max(__popcll(Mlo), __popcll(Mhi));   // >=1 (diag)

    // ---- Gather this warp's 64-feature slice: 2 independent chains --------
    const float2* xb = reinterpret_cast<const float2*>(xg + (size_t)b * AT * NF);
    const int fo = h * 32 + lane;             // float2 offset within a row

    float2 a0 = make_float2(-CUDART_INF_F, -CUDART_INF_F);
    float2 a1 = a0;

    #pragma unroll 4
    for (int k = 0; k < kmax; ++k) {
        // Peel one index per chain; exhausted chain -> self row (harmless).
        int jA = i, jB = i;
        if (Mlo) { const int p = __ffsll(Mlo) - 1; jA = col_lo(p); Mlo &= Mlo - 1; }
        if (Mhi) { const int p = __ffsll(Mhi) - 1; jB = col_hi(p); Mhi &= Mhi - 1; }
        const float2 vA = __ldg(xb + (size_t)jA * 64 + fo);
        const float2 vB = __ldg(xb + (size_t)jB * 64 + fo);
        a0 = fmax2(a0, vA);
        a1 = fmax2(a1, vB);
    }

    outw[lane] = fmax2(a0, a1);
}

extern "C" void kernel_launch(void* const* d_in, const int* in_sizes, int n_in,
                              void* d_out, int out_size)
{
    const float* node_features = (const float*)d_in[0];
    const float* laplacian     = (const float*)d_in[1];
    const int*   mol_slice     = (const int*)d_in[2];
    // d_in[3] = l_slice (unused)

    float* out = (float*)d_out;

    const int B = 64;
    const int total_warps = B * AT * 2;       // 16384 warps, half-row each
    const int blocks = total_warps / (THREADS / 32);  // 2048
    graph_pool_mol_kernel<<<blocks, THREADS>>>(
        node_features, laplacian, mol_slice, out);
}

// round 9
// speedup vs baseline: 1.2330x; 1.2330x over previous
#include <cuda_runtime.h>
#include <math_constants.h>

// GraphPoolMol: masked neighborhood max-pool over graph Laplacian sparsity.
// B=64, MAX_ATOM=128, N_FEAT=128.
// out[b,i,f] = max_{j: L[b,i,j]!=0, j<n, i<n} x[b,j,f]; 0 if i>=n.
// diag(L)=1 => for i<n the mask always contains j=i, so cnt>=1 and the
// reference's "no neighbor" fallback never fires for valid rows.
//
// Warp-per-row, no smem/barriers. The 128-bit column mask is warp-uniform;
// lane s extracts the s-th set column ONCE (popc binary search), then the
// gather loop is just shfl-broadcast + LDG.128 + fmax: ~8 instr per neighbor,
// exactly cnt loads, zero peel, zero waste.

#define AT 128
#define NF 128
#define THREADS 128

__device__ __forceinline__ float4 fmax4(float4 a, float4 b) {
    return make_float4(fmaxf(a.x, b.x), fmaxf(a.y, b.y),
                       fmaxf(a.z, b.z), fmaxf(a.w, b.w));
}

// Position of the r-th (0-indexed) set bit of m. Garbage (but in-range) if
// r >= popc(m) — callers never consume those lanes.
__device__ __forceinline__ int nth_bit(unsigned m, int r) {
    int j = 0, c;
    c = __popc(m & 0xFFFFu); if (r >= c) { r -= c; m >>= 16; j = 16; }
    c = __popc(m & 0xFFu);   if (r >= c) { r -= c; m >>= 8;  j += 8; }
    c = __popc(m & 0xFu);    if (r >= c) { r -= c; m >>= 4;  j += 4; }
    c = __popc(m & 0x3u);    if (r >= c) { r -= c; m >>= 2;  j += 2; }
    c = (int)(m & 1u);       if (r >= c) {                   j += 1; }
    return j;
}

__global__ __launch_bounds__(THREADS, 12)
void graph_pool_mol_kernel(const float* __restrict__ xg,
                           const float* __restrict__ Lg,
                           const int* __restrict__ mol_slice,
                           float* __restrict__ outg)
{
    const int gw   = (blockIdx.x * THREADS + threadIdx.x) >> 5; // row id
    const int lane = threadIdx.x & 31;
    const int b    = gw >> 7;
    const int i    = gw & (AT - 1);

    const int n = __ldg(mol_slice + 2 * b);      // mol_slice[b,0] = n_atoms

    float4* outr = reinterpret_cast<float4*>(outg) + ((size_t)b * AT + i) * 32;

    if (i >= n) {                                 // padded row
        outr[lane] = make_float4(0.f, 0.f, 0.f, 0.f);
        return;
    }

    // ---- L row -> warp-uniform 128-bit mask (ballot word q: col = 4*bit+q)
    const float4 Lv = __ldg(reinterpret_cast<const float4*>(
                                Lg + ((size_t)b * AT + i) * AT) + lane);
    const int j0 = 4 * lane;
    const unsigned m0 = __ballot_sync(0xffffffffu, (Lv.x != 0.f) && (j0 + 0 < n));
    const unsigned m1 = __ballot_sync(0xffffffffu, (Lv.y != 0.f) && (j0 + 1 < n));
    const unsigned m2 = __ballot_sync(0xffffffffu, (Lv.z != 0.f) && (j0 + 2 < n));
    const unsigned m3 = __ballot_sync(0xffffffffu, (Lv.w != 0.f) && (j0 + 3 < n));

    const int c0 = __popc(m0), c1 = __popc(m1), c2 = __popc(m2);
    const int cnt = c0 + c1 + c2 + __popc(m3);    // >= 1 (diagonal)

    const float4* xb = reinterpret_cast<const float4*>(xg + (size_t)b * AT * NF);
    float4 acc0 = make_float4(-CUDART_INF_F, -CUDART_INF_F,
                              -CUDART_INF_F, -CUDART_INF_F);
    float4 acc1 = acc0;

    int done = 0;
    while (done < cnt) {                          // single pass unless cnt>32
        // Lane s extracts the (done+s)-th set column of the 128-bit mask.
        int t = done + lane;
        unsigned m = m0; int q = 0;
        if (t >= c0) { t -= c0; m = m1; q = 1;
            if (t >= c1) { t -= c1; m = m2; q = 2;
                if (t >= c2) { t -= c2; m = m3; q = 3; } } }
        const int jmine = 4 * nth_bit(m, min(t, 31)) + q;

        const int cm = min(cnt - done, 32);
        int k = 0;
        for (; k + 1 < cm; k += 2) {
            const int jA = __shfl_sync(0xffffffffu, jmine, k);
            const int jB = __shfl_sync(0xffffffffu, jmine, k + 1);
            const float4 vA = __ldg(xb + jA * 32 + lane);
            const float4 vB = __ldg(xb + jB * 32 + lane);
            acc0 = fmax4(acc0, vA);
            acc1 = fmax4(acc1, vB);
        }
        if (k < cm) {
            const int jA = __shfl_sync(0xffffffffu, jmine, k);
            acc0 = fmax4(acc0, __ldg(xb + jA * 32 + lane));
        }
        done += cm;
    }

    outr[lane] = fmax4(acc0, acc1);
}

extern "C" void kernel_launch(void* const* d_in, const int* in_sizes, int n_in,
                              void* d_out, int out_size)
{
    const float* node_features = (const float*)d_in[0];
    const float* laplacian     = (const float*)d_in[1];
    const int*   mol_slice     = (const int*)d_in[2];
    // d_in[3] = l_slice (unused)

    float* out = (float*)d_out;

    const int B = 64;
    const int total_warps = B * AT;               // 8192 warps, one per row
    const int blocks = total_warps / (THREADS / 32);   // 2048
    graph_pool_mol_kernel<<<blocks, THREADS>>>(
        node_features, laplacian, mol_slice, out);
}

// round 10
// speedup vs baseline: 1.2374x; 1.0036x over previous
#include <cuda_runtime.h>
#include <math_constants.h>

// GraphPoolMol: masked neighborhood max-pool over graph Laplacian sparsity.
// B=64, MAX_ATOM=128, N_FEAT=128.
// out[b,i,f] = max_{j: L[b,i,j]!=0, j<n, i<n} x[b,j,f]; 0 if i>=n.
// diag(L)=1 => for i<n the mask contains j=i (cnt>=1; fallback never fires),
// and padding gather slots with the self row never changes the max.
//
// Warp-per-row, no smem/barriers. Warp-uniform 128-bit mask; lane s extracts
// the s-th set column once; gather runs in batches of 8 independent LDG.128s
// (MLP=8) folded after issue. L-row load overlaps the n load (issued before
// the early-exit branch).

#define AT 128
#define NF 128
#define THREADS 128

__device__ __forceinline__ float4 fmax4(float4 a, float4 b) {
    return make_float4(fmaxf(a.x, b.x), fmaxf(a.y, b.y),
                       fmaxf(a.z, b.z), fmaxf(a.w, b.w));
}

// Position of the r-th (0-indexed) set bit of m. Returns a value in [0,31]
// (garbage but in-range when r >= popc(m); such lanes are never consumed).
__device__ __forceinline__ int nth_bit(unsigned m, int r) {
    int j = 0, c;
    c = __popc(m & 0xFFFFu); if (r >= c) { r -= c; m >>= 16; j = 16; }
    c = __popc(m & 0xFFu);   if (r >= c) { r -= c; m >>= 8;  j += 8; }
    c = __popc(m & 0xFu);    if (r >= c) { r -= c; m >>= 4;  j += 4; }
    c = __popc(m & 0x3u);    if (r >= c) { r -= c; m >>= 2;  j += 2; }
    c = (int)(m & 1u);       if (r >= c) {                   j += 1; }
    return j;
}

__global__ __launch_bounds__(THREADS, 8)
void graph_pool_mol_kernel(const float* __restrict__ xg,
                           const float* __restrict__ Lg,
                           const int* __restrict__ mol_slice,
                           float* __restrict__ outg)
{
    const int gw   = (blockIdx.x * THREADS + threadIdx.x) >> 5; // row id
    const int lane = threadIdx.x & 31;
    const int b    = gw >> 7;
    const int i    = gw & (AT - 1);

    // Issue BOTH long-latency loads before anything depends on either.
    const int n = __ldg(mol_slice + 2 * b);      // mol_slice[b,0] = n_atoms
    const float4 Lv = __ldg(reinterpret_cast<const float4*>(
                                Lg + ((size_t)b * AT + i) * AT) + lane);

    float4* outr = reinterpret_cast<float4*>(outg) + ((size_t)b * AT + i) * 32;

    if (i >= n) {                                 // padded row
        outr[lane] = make_float4(0.f, 0.f, 0.f, 0.f);
        return;
    }

    // ---- Warp-uniform 128-bit mask (ballot word q: col = 4*bit + q) -------
    const int j0 = 4 * lane;
    const unsigned m0 = __ballot_sync(0xffffffffu, (Lv.x != 0.f) && (j0 + 0 < n));
    const unsigned m1 = __ballot_sync(0xffffffffu, (Lv.y != 0.f) && (j0 + 1 < n));
    const unsigned m2 = __ballot_sync(0xffffffffu, (Lv.z != 0.f) && (j0 + 2 < n));
    const unsigned m3 = __ballot_sync(0xffffffffu, (Lv.w != 0.f) && (j0 + 3 < n));

    const int c0 = __popc(m0), c1 = __popc(m1), c2 = __popc(m2);
    const int cnt = c0 + c1 + c2 + __popc(m3);    // >= 1 (diagonal)

    const float4* xb = reinterpret_cast<const float4*>(xg + (size_t)b * AT * NF);
    float4 acc0 = make_float4(-CUDART_INF_F, -CUDART_INF_F,
                              -CUDART_INF_F, -CUDART_INF_F);
    float4 acc1 = acc0;

    int done = 0;
    while (done < cnt) {                          // one pass unless cnt > 32
        // Lane s extracts the (done+s)-th set column.
        int t = done + lane;
        unsigned m = m0; int q = 0;
        if (t >= c0) { t -= c0; m = m1; q = 1;
            if (t >= c1) { t -= c1; m = m2; q = 2;
                if (t >= c2) { t -= c2; m = m3; q = 3; } } }
        const int jmine = 4 * nth_bit(m, min(t, 31)) + q;   // in [0,127]

        const int cm  = min(cnt - done, 32);
        const int cmp = (cm + 7) & ~7;            // padded batch bound

        for (int kb = 0; kb < cmp; kb += 8) {
            // 8 warp-uniform indices; slots past cm fall back to self row i.
            int jj[8];
            #pragma unroll
            for (int t8 = 0; t8 < 8; ++t8) {
                const int s  = kb + t8;
                const int js = __shfl_sync(0xffffffffu, jmine, s & 31);
                jj[t8] = (s < cm) ? js : i;
            }
            // 8 independent LDG.128s in flight (MLP = 8) ...
            float4 v0 = __ldg(xb + jj[0] * 32 + lane);
            float4 v1 = __ldg(xb + jj[1] * 32 + lane);
            float4 v2 = __ldg(xb + jj[2] * 32 + lane);
            float4 v3 = __ldg(xb + jj[3] * 32 + lane);
            float4 v4 = __ldg(xb + jj[4] * 32 + lane);
            float4 v5 = __ldg(xb + jj[5] * 32 + lane);
            float4 v6 = __ldg(xb + jj[6] * 32 + lane);
            float4 v7 = __ldg(xb + jj[7] * 32 + lane);
            // ... then fold.
            acc0 = fmax4(acc0, v0);
            acc1 = fmax4(acc1, v1);
            acc0 = fmax4(acc0, v2);
            acc1 = fmax4(acc1, v3);
            acc0 = fmax4(acc0, v4);
            acc1 = fmax4(acc1, v5);
            acc0 = fmax4(acc0, v6);
            acc1 = fmax4(acc1, v7);
        }
        done += cm;
    }

    outr[lane] = fmax4(acc0, acc1);
}

extern "C" void kernel_launch(void* const* d_in, const int* in_sizes, int n_in,
                              void* d_out, int out_size)
{
    const float* node_features = (const float*)d_in[0];
    const float* laplacian     = (const float*)d_in[1];
    const int*   mol_slice     = (const int*)d_in[2];
    // d_in[3] = l_slice (unused)

    float* out = (float*)d_out;

    const int B = 64;
    const int total_warps = B * AT;               // 8192 warps, one per row
    const int blocks = total_warps / (THREADS / 32);   // 2048
    graph_pool_mol_kernel<<<blocks, THREADS>>>(
        node_features, laplacian, mol_slice, out);
}

// round 11
// speedup vs baseline: 1.2694x; 1.0258x over previous
#include <cuda_runtime.h>
#include <math_constants.h>

// GraphPoolMol: masked neighborhood max-pool over graph Laplacian sparsity.
// B=64, MAX_ATOM=128, N_FEAT=128.
// out[b,i,f] = max_{j: L[b,i,j]!=0, j<n, i<n} x[b,j,f]; 0 if i>=n.
// diag(L)=1 => for i<n the mask contains j=i (cnt>=1), so the reference's
// "no neighbor" fallback never fires for valid rows, and repeating a valid
// neighbor in the gather never changes the max.
//
// Locality design: one block = 32 consecutive rows of ONE batch (512 thr,
// 16 warps, 2 rows/warp). All gathers of the block read the same 64 KB x[b],
// which lives in L1 after first touch -> L2 request flood eliminated.

#define AT 128
#define NF 128
#define THREADS 512

__device__ __forceinline__ float4 fmax4(float4 a, float4 b) {
    return make_float4(fmaxf(a.x, b.x), fmaxf(a.y, b.y),
                       fmaxf(a.z, b.z), fmaxf(a.w, b.w));
}

// Position of the r-th (0-indexed) set bit of m; in-range garbage when
// r >= popc(m) (those lanes are never consumed).
__device__ __forceinline__ int nth_bit(unsigned m, int r) {
    int j = 0, c;
    c = __popc(m & 0xFFFFu); if (r >= c) { r -= c; m >>= 16; j = 16; }
    c = __popc(m & 0xFFu);   if (r >= c) { r -= c; m >>= 8;  j += 8; }
    c = __popc(m & 0xFu);    if (r >= c) { r -= c; m >>= 4;  j += 4; }
    c = __popc(m & 0x3u);    if (r >= c) { r -= c; m >>= 2;  j += 2; }
    c = (int)(m & 1u);       if (r >= c) {                   j += 1; }
    return j;
}

// Masked max over one row given its (warp-uniform) 128-bit column mask.
// Requires cnt >= 1 (guaranteed by the unit diagonal for valid rows).
__device__ __forceinline__ float4 pool_row(const float4* __restrict__ xb,
                                           int lane,
                                           unsigned m0, unsigned m1,
                                           unsigned m2, unsigned m3)
{
    const int c0 = __popc(m0), c1 = __popc(m1), c2 = __popc(m2);
    const int cnt = c0 + c1 + c2 + __popc(m3);

    float4 acc0 = make_float4(-CUDART_INF_F, -CUDART_INF_F,
                              -CUDART_INF_F, -CUDART_INF_F);
    float4 acc1 = acc0;

    int done = 0;
    while (done < cnt) {                       // one pass unless cnt > 32
        // Lane s extracts the (done+s)-th set column (col = 4*bit + word).
        int t = done + lane;
        unsigned m = m0; int q = 0;
        if (t >= c0) { t -= c0; m = m1; q = 1;
            if (t >= c1) { t -= c1; m = m2; q = 2;
                if (t >= c2) { t -= c2; m = m3; q = 3; } } }
        const int jmine = 4 * nth_bit(m, min(t, 31)) + q;   // in [0,127]

        const int cm  = min(cnt - done, 32);
        const int cmp = (cm + 7) & ~7;

        for (int kb = 0; kb < cmp; kb += 8) {
            // Clamped source lane pads the batch by repeating the last
            // valid neighbor (harmless for max).
            int jj[8];
            #pragma unroll
            for (int u = 0; u < 8; ++u)
                jj[u] = __shfl_sync(0xffffffffu, jmine, min(kb + u, cm - 1));
            float4 v0 = __ldg(xb + jj[0] * 32 + lane);
            float4 v1 = __ldg(xb + jj[1] * 32 + lane);
            float4 v2 = __ldg(xb + jj[2] * 32 + lane);
            float4 v3 = __ldg(xb + jj[3] * 32 + lane);
            float4 v4 = __ldg(xb + jj[4] * 32 + lane);
            float4 v5 = __ldg(xb + jj[5] * 32 + lane);
            float4 v6 = __ldg(xb + jj[6] * 32 + lane);
            float4 v7 = __ldg(xb + jj[7] * 32 + lane);
            acc0 = fmax4(acc0, v0);
            acc1 = fmax4(acc1, v1);
            acc0 = fmax4(acc0, v2);
            acc1 = fmax4(acc1, v3);
            acc0 = fmax4(acc0, v4);
            acc1 = fmax4(acc1, v5);
            acc0 = fmax4(acc0, v6);
            acc1 = fmax4(acc1, v7);
        }
        done += cm;
    }
    return fmax4(acc0, acc1);
}

__global__ __launch_bounds__(THREADS, 2)
void graph_pool_mol_kernel(const float* __restrict__ xg,
                           const float* __restrict__ Lg,
                           const int* __restrict__ mol_slice,
                           float* __restrict__ outg)
{
    const int b    = blockIdx.x >> 2;          // batch
    const int base = (blockIdx.x & 3) * 32;    // row quad within batch
    const int wid  = threadIdx.x >> 5;         // 0..15
    const int lane = threadIdx.x & 31;
    const int i0   = base + 2 * wid;           // this warp's two rows
    const int i1   = i0 + 1;

    const int n = __ldg(mol_slice + 2 * b);    // mol_slice[b,0] = n_atoms

    float4* outb = reinterpret_cast<float4*>(outg) + (size_t)b * AT * 32;
    const float4 zero = make_float4(0.f, 0.f, 0.f, 0.f);

    if (i0 >= n) {                             // both rows padded
        outb[(size_t)i0 * 32 + lane] = zero;
        outb[(size_t)i1 * 32 + lane] = zero;
        return;
    }
    const bool v1 = (i1 < n);                  // warp-uniform

    // ---- Load both L rows up front (independent, one epoch) ---------------
    const float4* Lb4 = reinterpret_cast<const float4*>(Lg + (size_t)b * AT * AT);
    const float4 L0 = __ldg(Lb4 + (size_t)i0 * 32 + lane);
    const float4 L1 = v1 ? __ldg(Lb4 + (size_t)i1 * 32 + lane) : zero;

    // ---- Ballot masks (word q: col = 4*bit + q) ----------------------------
    const int j0 = 4 * lane;
    const bool c0 = (j0 + 0) < n, c1 = (j0 + 1) < n,
               c2 = (j0 + 2) < n, c3 = (j0 + 3) < n;

    const unsigned a0 = __ballot_sync(0xffffffffu, (L0.x != 0.f) && c0);
    const unsigned a1 = __ballot_sync(0xffffffffu, (L0.y != 0.f) && c1);
    const unsigned a2 = __ballot_sync(0xffffffffu, (L0.z != 0.f) && c2);
    const unsigned a3 = __ballot_sync(0xffffffffu, (L0.w != 0.f) && c3);
    const unsigned b0 = __ballot_sync(0xffffffffu, (L1.x != 0.f) && c0);
    const unsigned b1 = __ballot_sync(0xffffffffu, (L1.y != 0.f) && c1);
    const unsigned b2 = __ballot_sync(0xffffffffu, (L1.z != 0.f) && c2);
    const unsigned b3 = __ballot_sync(0xffffffffu, (L1.w != 0.f) && c3);

    // ---- Gather both rows from the (L1-resident) x[b] tile -----------------
    const float4* xb = reinterpret_cast<const float4*>(xg + (size_t)b * AT * NF);

    outb[(size_t)i0 * 32 + lane] = pool_row(xb, lane, a0, a1, a2, a3);
    outb[(size_t)i1 * 32 + lane] = v1 ? pool_row(xb, lane, b0, b1, b2, b3)
                                      : zero;
}

extern "C" void kernel_launch(void* const* d_in, const int* in_sizes, int n_in,
                              void* d_out, int out_size)
{
    const float* node_features = (const float*)d_in[0];
    const float* laplacian     = (const float*)d_in[1];
    const int*   mol_slice     = (const int*)d_in[2];
    // d_in[3] = l_slice (unused)

    float* out = (float*)d_out;

    const int B = 64;
    graph_pool_mol_kernel<<<B * 4, THREADS>>>(   // 256 blocks, 32 rows each
        node_features, laplacian, mol_slice, out);
}